// round 15
// baseline (speedup 1.0000x reference)
#include <cuda_runtime.h>
#include <cuda_fp16.h>
#include <math.h>
#include <stdint.h>

// Problem constants
static const int NN = 50000;
static const int FF = 64;
static const int HH = 256;
static const int EE = 1600000;
static const int FH = 320;                     // FF + HH
static const int NB_SCAN = (NN + 1023) / 1024; // 49
static const int MBLK = (NN + 127) / 128;      // 391
static const int NCB = (NN + 7) / 8;           // 6250 combine blocks
// node-half split (8-aligned and 128-aligned)
static const int H0N = 24960;
static const int H0B = H0N / 8;                // 3120 combine blocks
static const int H1B = NCB - H0B;              // 3130
static const int H0M = H0N / 128;              // 195 GEMM row-blocks
static const int H1M = MBLK - H0M;             // 196

// ---------------- scratch (__device__ globals; allocation-free) ----------------
__device__ int   d_cnt[NN];
__device__ int   d_rowptr[NN + 1];
__device__ int   d_fill[NN];
__device__ int   d_col[EE];
__device__ int   d_bsum[64];
__device__ float d_deg[NN];
__device__ float d_g1[NN];
// fp16 activation buffers (GEMM A operands)
__device__ __align__(16) __half d_h1[NN * HH];    // tanh(gin0)
__device__ __align__(16) __half d_hcat[NN * FH];  // [x | h1b]
__device__ __align__(16) __half d_h2[NN * HH];    // relu(sage0)
// fp16 projection outputs
__device__ __align__(16) __half d_Pl[NN * HH];
__device__ __align__(16) __half d_Pr[NN * HH];
// fp16 weights
__device__ __align__(16) __half d_gw1[HH * HH];     // [256,256]
__device__ __align__(16) __half d_w0[FH * 2 * HH];  // [320,512] = [Wl0|Wr0]
__device__ __align__(16) __half d_w1[HH * 2 * HH];  // [256,512] = [Wl1|Wr1]

// HW tanh (sm_75+): single MUFU op, ~2^-11 accuracy
__device__ __forceinline__ float htanh(float x) {
    float r;
    asm("tanh.approx.f32 %0, %1;" : "=f"(r) : "f"(x));
    return r;
}

// ---------------- CSR build ----------------
// merged: degree count + GIN0 scatter (one edge-list pass)
__global__ void k_count_g1(const int* __restrict__ src, const int* __restrict__ dst,
                           const float* __restrict__ x1) {
    int e = blockIdx.x * blockDim.x + threadIdx.x;
    if (e < EE) {
        int d = dst[e];
        atomicAdd(&d_cnt[d], 1);
        atomicAdd(&d_g1[d], x1[src[e]]);
    }
}

__global__ void k_scan1() {
    __shared__ int sh[1024];
    int tid = threadIdx.x;
    int i = blockIdx.x * 1024 + tid;
    int v = (i < NN) ? d_cnt[i] : 0;
    sh[tid] = v;
    __syncthreads();
#pragma unroll
    for (int off = 1; off < 1024; off <<= 1) {
        int t = (tid >= off) ? sh[tid - off] : 0;
        __syncthreads();
        sh[tid] += t;
        __syncthreads();
    }
    if (i < NN) d_rowptr[i] = sh[tid] - v; // exclusive
    if (tid == 1023) d_bsum[blockIdx.x] = sh[1023];
}

// scan3 with scan2 folded in
__global__ void k_scan3() {
    __shared__ int s_pre[NB_SCAN];
    if (threadIdx.x == 0) {
        int run = 0;
#pragma unroll 1
        for (int b = 0; b < NB_SCAN; b++) {
            int t = d_bsum[b];
            s_pre[b] = run;
            run += t;
        }
    }
    __syncthreads();
    int i = blockIdx.x * blockDim.x + threadIdx.x;
    if (i < NN) {
        int r = d_rowptr[i] + s_pre[i >> 10];
        d_rowptr[i] = r;
        d_fill[i] = r;
        float c = (float)d_cnt[i];
        d_deg[i] = fmaxf(c, 1.0f);
    } else if (i == NN) {
        d_rowptr[NN] = EE;
    }
}

__global__ void k_fill(const int* __restrict__ src, const int* __restrict__ dst) {
    int e = blockIdx.x * blockDim.x + threadIdx.x;
    if (e < EE) {
        int pos = atomicAdd(&d_fill[dst[e]], 1);
        d_col[pos] = src[e];
    }
}

// ---------------- weight convert (all 5 weights in one kernel) ----------------
__global__ void k_cvt_all(const float* __restrict__ gw1,
                          const float* __restrict__ wl0, const float* __restrict__ wr0,
                          const float* __restrict__ wl1, const float* __restrict__ wr1) {
    int i = blockIdx.x * blockDim.x + threadIdx.x;
    if (i >= 360448) return;
    const float* W; __half* D; int pitch, off, base;
    if (i < 65536)       { W = gw1; D = d_gw1; pitch = 256; off = 0;   base = 0; }
    else if (i < 147456) { W = wl0; D = d_w0;  pitch = 512; off = 0;   base = 65536; }
    else if (i < 229376) { W = wr0; D = d_w0;  pitch = 512; off = 256; base = 147456; }
    else if (i < 294912) { W = wl1; D = d_w1;  pitch = 512; off = 0;   base = 229376; }
    else                 { W = wr1; D = d_w1;  pitch = 512; off = 256; base = 294912; }
    int j = i - base;
    int k = j >> 8, c = j & 255;
    D[(size_t)k * pitch + off + c] = __float2half_rn(W[j]);
}

// x [N,64] fp32 -> hcat fp16 cols 0..63 (pitch 320)
__global__ void k_split_x(const float* __restrict__ x) {
    int i = blockIdx.x * blockDim.x + threadIdx.x;
    if (i >= NN * FF) return;
    int r = i >> 6;
    int c = i & 63;
    d_hcat[(size_t)r * FH + c] = __float2half_rn(x[i]);
}

// warp per node: h1[node, :] = tanh(g * w0 + b0)
__global__ void k_gin0_act(const float* __restrict__ x1,
                           const float* __restrict__ w0, const float* __restrict__ b0) {
    int node = blockIdx.x * 8 + (threadIdx.x >> 5);
    if (node >= NN) return;
    int lane = threadIdx.x & 31;
    float g = d_g1[node] + x1[node]; // self term folded in
    int c = lane * 8;
    const float4* w4 = (const float4*)&w0[c];
    const float4* b4 = (const float4*)&b0[c];
    float4 w_0 = w4[0], w_1 = w4[1];
    float4 b_0 = b4[0], b_1 = b4[1];
    float a[8];
    a[0] = htanh(fmaf(g, w_0.x, b_0.x));
    a[1] = htanh(fmaf(g, w_0.y, b_0.y));
    a[2] = htanh(fmaf(g, w_0.z, b_0.z));
    a[3] = htanh(fmaf(g, w_0.w, b_0.w));
    a[4] = htanh(fmaf(g, w_1.x, b_1.x));
    a[5] = htanh(fmaf(g, w_1.y, b_1.y));
    a[6] = htanh(fmaf(g, w_1.z, b_1.z));
    a[7] = htanh(fmaf(g, w_1.w, b_1.w));
    uint4 r;
    *(__half2*)&r.x = __floats2half2_rn(a[0], a[1]);
    *(__half2*)&r.y = __floats2half2_rn(a[2], a[3]);
    *(__half2*)&r.z = __floats2half2_rn(a[4], a[5]);
    *(__half2*)&r.w = __floats2half2_rn(a[6], a[7]);
    *(uint4*)&d_h1[(size_t)node * HH + c] = r;
}

// ---------------- fused gather + combine (warp per node, uint4 loads) ----------------
__device__ __forceinline__ void acc_u4(float* a, uint4 u) {
    float2 f;
    f = __half22float2(*(__half2*)&u.x); a[0] += f.x; a[1] += f.y;
    f = __half22float2(*(__half2*)&u.y); a[2] += f.x; a[3] += f.y;
    f = __half22float2(*(__half2*)&u.z); a[4] += f.x; a[5] += f.y;
    f = __half22float2(*(__half2*)&u.w); a[6] += f.x; a[7] += f.y;
}

__device__ __forceinline__ void gather_sum(float* a, const uint4* __restrict__ P4,
                                           int beg, int end, int lane) {
    int j = beg;
    for (; j + 3 < end; j += 4) {
        int s0 = d_col[j], s1 = d_col[j + 1], s2 = d_col[j + 2], s3 = d_col[j + 3];
        uint4 u0 = P4[(size_t)s0 * 32 + lane];
        uint4 u1 = P4[(size_t)s1 * 32 + lane];
        uint4 u2 = P4[(size_t)s2 * 32 + lane];
        uint4 u3 = P4[(size_t)s3 * 32 + lane];
        acc_u4(a, u0); acc_u4(a, u1); acc_u4(a, u2); acc_u4(a, u3);
    }
    for (; j < end; j++) acc_u4(a, P4[(size_t)d_col[j] * 32 + lane]);
}

__device__ __forceinline__ uint4 pack8h(const float* a) {
    uint4 r;
    *(__half2*)&r.x = __floats2half2_rn(a[0], a[1]);
    *(__half2*)&r.y = __floats2half2_rn(a[2], a[3]);
    *(__half2*)&r.z = __floats2half2_rn(a[4], a[5]);
    *(__half2*)&r.w = __floats2half2_rn(a[6], a[7]);
    return r;
}

// GIN1: hcat[64..319] = tanh(P[node] + sum_nbr P[nbr] + b)
__global__ void k_comb_gin(const __half* __restrict__ P,
                           const float* __restrict__ bias, int nodeOff) {
    int node = nodeOff + blockIdx.x * 8 + (threadIdx.x >> 5);
    if (node >= NN) return;
    int lane = threadIdx.x & 31;
    const uint4* P4 = (const uint4*)P;
    float a[8] = {0, 0, 0, 0, 0, 0, 0, 0};
    gather_sum(a, P4, d_rowptr[node], d_rowptr[node + 1], lane);
    acc_u4(a, P4[(size_t)node * 32 + lane]); // self
    const float4* b4 = (const float4*)&bias[lane * 8];
    float4 b0 = b4[0], b1 = b4[1];
    a[0] = htanh(a[0] + b0.x); a[1] = htanh(a[1] + b0.y);
    a[2] = htanh(a[2] + b0.z); a[3] = htanh(a[3] + b0.w);
    a[4] = htanh(a[4] + b1.x); a[5] = htanh(a[5] + b1.y);
    a[6] = htanh(a[6] + b1.z); a[7] = htanh(a[7] + b1.w);
    *(uint4*)&d_hcat[(size_t)node * FH + 64 + lane * 8] = pack8h(a);
}

// SAGE: out = relu(sum_nbr Pl[nbr]/deg + b + Pr[node])
__global__ void k_comb_sage(const __half* __restrict__ Pl,
                            const __half* __restrict__ Pr,
                            const float* __restrict__ bias,
                            __half* __restrict__ outp, int nodeOff) {
    int node = nodeOff + blockIdx.x * 8 + (threadIdx.x >> 5);
    if (node >= NN) return;
    int lane = threadIdx.x & 31;
    const uint4* Pl4 = (const uint4*)Pl;
    const uint4* Pr4 = (const uint4*)Pr;
    float a[8] = {0, 0, 0, 0, 0, 0, 0, 0};
    gather_sum(a, Pl4, d_rowptr[node], d_rowptr[node + 1], lane);
    float inv = 1.0f / d_deg[node];
    float r[8] = {0, 0, 0, 0, 0, 0, 0, 0};
    acc_u4(r, Pr4[(size_t)node * 32 + lane]);
    const float4* b4 = (const float4*)&bias[lane * 8];
    float4 b0 = b4[0], b1 = b4[1];
    a[0] = fmaxf(a[0] * inv + b0.x + r[0], 0.f);
    a[1] = fmaxf(a[1] * inv + b0.y + r[1], 0.f);
    a[2] = fmaxf(a[2] * inv + b0.z + r[2], 0.f);
    a[3] = fmaxf(a[3] * inv + b0.w + r[3], 0.f);
    a[4] = fmaxf(a[4] * inv + b1.x + r[4], 0.f);
    a[5] = fmaxf(a[5] * inv + b1.y + r[5], 0.f);
    a[6] = fmaxf(a[6] * inv + b1.z + r[6], 0.f);
    a[7] = fmaxf(a[7] * inv + b1.w + r[7], 0.f);
    *(uint4*)&outp[(size_t)node * HH + lane * 8] = pack8h(a);
}

// SAGE final + fused head: out[node] = relu(...) . lw + lb  (256 -> 2)
__global__ void k_comb_sage_out(const __half* __restrict__ Pl,
                                const __half* __restrict__ Pr,
                                const float* __restrict__ bias,
                                const float* __restrict__ lw,
                                const float* __restrict__ lb,
                                float* __restrict__ out) {
    int node = blockIdx.x * 8 + (threadIdx.x >> 5);
    if (node >= NN) return;
    int lane = threadIdx.x & 31;
    const uint4* Pl4 = (const uint4*)Pl;
    const uint4* Pr4 = (const uint4*)Pr;
    float a[8] = {0, 0, 0, 0, 0, 0, 0, 0};
    gather_sum(a, Pl4, d_rowptr[node], d_rowptr[node + 1], lane);
    float inv = 1.0f / d_deg[node];
    float r[8] = {0, 0, 0, 0, 0, 0, 0, 0};
    acc_u4(r, Pr4[(size_t)node * 32 + lane]);
    const float4* b4 = (const float4*)&bias[lane * 8];
    float4 b0 = b4[0], b1 = b4[1];
    a[0] = fmaxf(a[0] * inv + b0.x + r[0], 0.f);
    a[1] = fmaxf(a[1] * inv + b0.y + r[1], 0.f);
    a[2] = fmaxf(a[2] * inv + b0.z + r[2], 0.f);
    a[3] = fmaxf(a[3] * inv + b0.w + r[3], 0.f);
    a[4] = fmaxf(a[4] * inv + b1.x + r[4], 0.f);
    a[5] = fmaxf(a[5] * inv + b1.y + r[5], 0.f);
    a[6] = fmaxf(a[6] * inv + b1.z + r[6], 0.f);
    a[7] = fmaxf(a[7] * inv + b1.w + r[7], 0.f);
    int c = lane * 8;
    float p0 = 0.f, p1 = 0.f;
#pragma unroll
    for (int i = 0; i < 8; i++) {
        p0 += a[i] * lw[(c + i) * 2 + 0];
        p1 += a[i] * lw[(c + i) * 2 + 1];
    }
#pragma unroll
    for (int o = 16; o > 0; o >>= 1) {
        p0 += __shfl_down_sync(0xFFFFFFFFu, p0, o);
        p1 += __shfl_down_sync(0xFFFFFFFFu, p1, o);
    }
    if (lane == 0) {
        out[node * 2 + 0] = p0 + lb[0];
        out[node * 2 + 1] = p1 + lb[1];
    }
}

// ---------------- fp16 tensor-core GEMM, single weight panel, 3-stage pipeline ----------------
#define CP_ASYNC16(dst, src, sz) \
    asm volatile("cp.async.cg.shared.global [%0], [%1], 16, %2;" \
                 :: "r"(dst), "l"(src), "r"(sz))
#define CP_COMMIT() asm volatile("cp.async.commit_group;")
#define CP_WAIT2()  asm volatile("cp.async.wait_group 2;")
#define CP_WAIT1()  asm volatile("cp.async.wait_group 1;")
#define CP_WAIT0()  asm volatile("cp.async.wait_group 0;")

static const int APITCH = 40;   // halves per A row (32 data + 8 pad)
static const int BPITCH = 136;  // halves per B row (128 data + 8 pad)
static const int AS_ST = 128 * APITCH;   // 5120 halves per A stage
static const int BS_ST = 32 * BPITCH;    // 4352 halves per B stage
static const int B_OFF = 3 * AS_ST;      // 15360
static const int SMEM_BYTES = (3 * AS_ST + 3 * BS_ST) * 2; // 56832

__global__ void __launch_bounds__(256, 2)
k_mma(const __half* __restrict__ A, const __half* __restrict__ B,
      int K, int Nc,
      __half* __restrict__ C0, __half* __restrict__ C1, int M, int rowOff)
{
    extern __shared__ __half sm[];
    const int tid = threadIdx.x;
    const int lane = tid & 31, warp = tid >> 5;
    const int wm = warp >> 1, wn = warp & 1;  // 4 x 2 warp grid, 32x64 per warp
    const int blockRow = rowOff + blockIdx.y * 128;
    const int blockCol = blockIdx.x * 128;

    const int nIter = K >> 5;   // BK = 32

    uint32_t sm_base = (uint32_t)__cvta_generic_to_shared(sm);

    auto prefetch = [&](int it) {
        int st = it % 3;
        int kk = it << 5;
#pragma unroll
        for (int i = 0; i < 2; i++) {
            int idx = tid + i * 256;
            int row = idx >> 2, ch = idx & 3;
            int gr = blockRow + row;
            int ok = (gr < M) ? 16 : 0;
            const __half* srcp = A + (size_t)(ok ? gr : 0) * K + kk + ch * 8;
            uint32_t dstp = sm_base + (st * AS_ST + row * APITCH + ch * 8) * 2;
            CP_ASYNC16(dstp, srcp, ok);
        }
#pragma unroll
        for (int i = 0; i < 2; i++) {
            int idx = tid + i * 256;
            int row = idx >> 4, ch = idx & 15;
            const __half* srcp = B + (size_t)(kk + row) * Nc + blockCol + ch * 8;
            uint32_t dstp = sm_base + (B_OFF + st * BS_ST + row * BPITCH + ch * 8) * 2;
            CP_ASYNC16(dstp, srcp, 16);
        }
    };

    float c[2][8][4];
#pragma unroll
    for (int mt = 0; mt < 2; mt++)
#pragma unroll
        for (int nt = 0; nt < 8; nt++)
#pragma unroll
            for (int q = 0; q < 4; q++) c[mt][nt][q] = 0.f;

    prefetch(0); CP_COMMIT();
    if (nIter > 1) { prefetch(1); CP_COMMIT(); }

#pragma unroll 1
    for (int it = 0; it < nIter; it++) {
        if (it + 2 < nIter) {
            prefetch(it + 2);
            CP_COMMIT();
            CP_WAIT2();
        } else if (it + 1 < nIter) {
            CP_WAIT1();
        } else {
            CP_WAIT0();
        }
        __syncthreads();

        const int st = it % 3;
        const __half* as = sm + st * AS_ST;
        const __half* bs = sm + B_OFF + st * BS_ST;
#pragma unroll
        for (int ks = 0; ks < 2; ks++) {
            uint32_t af[2][4], bfr[4][4];
#pragma unroll
            for (int mt = 0; mt < 2; mt++) {
                int row = wm * 32 + mt * 16 + (lane & 15);
                int col = ks * 16 + (lane >> 4) * 8;
                uint32_t addr = (uint32_t)__cvta_generic_to_shared(&as[row * APITCH + col]);
                asm volatile(
                    "ldmatrix.sync.aligned.m8n8.x4.shared.b16 {%0,%1,%2,%3}, [%4];"
                    : "=r"(af[mt][0]), "=r"(af[mt][1]), "=r"(af[mt][2]), "=r"(af[mt][3])
                    : "r"(addr));
            }
#pragma unroll
            for (int bt = 0; bt < 4; bt++) {
                int row = ks * 16 + (lane & 15);
                int col = wn * 64 + bt * 16 + (lane >> 4) * 8;
                uint32_t addr = (uint32_t)__cvta_generic_to_shared(&bs[row * BPITCH + col]);
                asm volatile(
                    "ldmatrix.sync.aligned.m8n8.x4.trans.shared.b16 {%0,%1,%2,%3}, [%4];"
                    : "=r"(bfr[bt][0]), "=r"(bfr[bt][1]), "=r"(bfr[bt][2]), "=r"(bfr[bt][3])
                    : "r"(addr));
            }
#pragma unroll
            for (int mt = 0; mt < 2; mt++)
#pragma unroll
                for (int nt = 0; nt < 8; nt++) {
                    const uint32_t b0 = bfr[nt >> 1][(nt & 1) * 2];
                    const uint32_t b1 = bfr[nt >> 1][(nt & 1) * 2 + 1];
                    asm volatile(
                        "mma.sync.aligned.m16n8k16.row.col.f32.f16.f16.f32 "
                        "{%0,%1,%2,%3}, {%4,%5,%6,%7}, {%8,%9}, {%0,%1,%2,%3};"
                        : "+f"(c[mt][nt][0]), "+f"(c[mt][nt][1]),
                          "+f"(c[mt][nt][2]), "+f"(c[mt][nt][3])
                        : "r"(af[mt][0]), "r"(af[mt][1]), "r"(af[mt][2]), "r"(af[mt][3]),
                          "r"(b0), "r"(b1));
                }
        }
        __syncthreads();
    }

    // epilogue: fp16 stores
#pragma unroll
    for (int mt = 0; mt < 2; mt++) {
#pragma unroll
        for (int half_ = 0; half_ < 2; half_++) {
            int row = blockRow + wm * 32 + mt * 16 + half_ * 8 + (lane >> 2);
            if (row >= M) continue;
#pragma unroll
            for (int nt = 0; nt < 8; nt++) {
                int gcol = blockCol + wn * 64 + nt * 8 + (lane & 3) * 2;
                __half2 hv = __floats2half2_rn(c[mt][nt][half_ * 2 + 0],
                                               c[mt][nt][half_ * 2 + 1]);
                __half* Cp = (gcol < 256) ? C0 : C1;
                int cc = gcol & 255;
                *(__half2*)&Cp[(size_t)row * 256 + cc] = hv;
            }
        }
    }
}

// ---------------- launch ----------------
extern "C" void kernel_launch(void* const* d_in, const int* in_sizes, int n_in,
                              void* d_out, int out_size) {
    (void)in_sizes; (void)n_in; (void)out_size;
    const float* x   = (const float*)d_in[0];
    const float* x1  = (const float*)d_in[1];
    const int*   ei  = (const int*)d_in[2];
    const int*   src = ei;
    const int*   dst = ei + EE;
    const float* gw0 = (const float*)d_in[3];
    const float* gb0 = (const float*)d_in[4];
    const float* gw1 = (const float*)d_in[5];
    const float* gb1 = (const float*)d_in[6];
    const float* wl0 = (const float*)d_in[7];
    const float* bl0 = (const float*)d_in[8];
    const float* wr0 = (const float*)d_in[9];
    const float* wl1 = (const float*)d_in[10];
    const float* bl1 = (const float*)d_in[11];
    const float* wr1 = (const float*)d_in[12];
    const float* lw  = (const float*)d_in[13];
    const float* lb  = (const float*)d_in[14];
    float* out = (float*)d_out;

    cudaFuncSetAttribute(k_mma, cudaFuncAttributeMaxDynamicSharedMemorySize, SMEM_BYTES);

    __half *p_h1, *p_hcat, *p_h2, *p_Pl, *p_Pr, *p_gw1, *p_w0, *p_w1;
    cudaGetSymbolAddress((void**)&p_h1, d_h1);
    cudaGetSymbolAddress((void**)&p_hcat, d_hcat);
    cudaGetSymbolAddress((void**)&p_h2, d_h2);
    cudaGetSymbolAddress((void**)&p_Pl, d_Pl);
    cudaGetSymbolAddress((void**)&p_Pr, d_Pr);
    cudaGetSymbolAddress((void**)&p_gw1, d_gw1);
    cudaGetSymbolAddress((void**)&p_w0, d_w0);
    cudaGetSymbolAddress((void**)&p_w1, d_w1);

    void *p_cnt, *p_g1;
    cudaGetSymbolAddress(&p_cnt, d_cnt);
    cudaGetSymbolAddress(&p_g1, d_g1);

    // one-time aux stream + events
    static cudaStream_t s_aux = nullptr;
    static cudaEvent_t ev_fork = nullptr, ev_join = nullptr, ev_g1 = nullptr;
    static cudaEvent_t evA = nullptr, evB = nullptr, evC = nullptr,
                       evD = nullptr, evE = nullptr, evF = nullptr;
    if (s_aux == nullptr) {
        cudaStreamCreateWithFlags(&s_aux, cudaStreamNonBlocking);
        cudaEventCreateWithFlags(&ev_fork, cudaEventDisableTiming);
        cudaEventCreateWithFlags(&ev_join, cudaEventDisableTiming);
        cudaEventCreateWithFlags(&ev_g1, cudaEventDisableTiming);
        cudaEventCreateWithFlags(&evA, cudaEventDisableTiming);
        cudaEventCreateWithFlags(&evB, cudaEventDisableTiming);
        cudaEventCreateWithFlags(&evC, cudaEventDisableTiming);
        cudaEventCreateWithFlags(&evD, cudaEventDisableTiming);
        cudaEventCreateWithFlags(&evE, cudaEventDisableTiming);
        cudaEventCreateWithFlags(&evF, cudaEventDisableTiming);
    }

    // ---- fork ----
    cudaEventRecord(ev_fork, 0);
    cudaStreamWaitEvent(s_aux, ev_fork, 0);

    // aux: weight cvt + x split (independent of CSR/g1)
    k_cvt_all<<<(360448 + 255) / 256, 256, 0, s_aux>>>(gw1, wl0, wr0, wl1, wr1);
    k_split_x<<<(NN * FF + 255) / 256, 256, 0, s_aux>>>(x);

    // main: merged count + g1 scatter (one edge pass), then scan/fill
    cudaMemsetAsync(p_cnt, 0, NN * sizeof(int), 0);
    cudaMemsetAsync(p_g1, 0, NN * sizeof(float), 0);
    k_count_g1<<<(EE + 255) / 256, 256>>>(src, dst, x1);
    cudaEventRecord(ev_g1, 0);
    k_scan1<<<NB_SCAN, 1024>>>();
    k_scan3<<<(NN + 1 + 255) / 256, 256>>>();
    k_fill<<<(EE + 255) / 256, 256>>>(src, dst);

    // aux: gin0 + GEMM1 once g1 is ready (overlaps scan/fill on main)
    cudaStreamWaitEvent(s_aux, ev_g1, 0);
    k_gin0_act<<<NCB, 256, 0, s_aux>>>(x1, gw0, gb0);
    k_mma<<<dim3(2, MBLK), 256, SMEM_BYTES, s_aux>>>(p_h1, p_gw1, HH, HH,
                                                     p_Pl, nullptr, NN, 0);
    cudaEventRecord(ev_join, s_aux);

    // ---- join (GEMM1 + CSR ready) ----
    cudaStreamWaitEvent(0, ev_join, 0);

    // ---- pipelined comb_gin -> GEMM2 across node halves ----
    k_comb_gin<<<H0B, 256>>>(p_Pl, gb1, 0);
    cudaEventRecord(evA, 0);
    k_comb_gin<<<H1B, 256>>>(p_Pl, gb1, H0N);
    cudaEventRecord(evB, 0);

    cudaStreamWaitEvent(s_aux, evA, 0);
    k_mma<<<dim3(4, H0M), 256, SMEM_BYTES, s_aux>>>(p_hcat, p_w0, FH, 512,
                                                    p_Pl, p_Pr, NN, 0);
    cudaStreamWaitEvent(s_aux, evB, 0);
    k_mma<<<dim3(4, H1M), 256, SMEM_BYTES, s_aux>>>(p_hcat, p_w0, FH, 512,
                                                    p_Pl, p_Pr, NN, H0N);
    cudaEventRecord(evC, s_aux);

    // ---- pipelined comb_sage -> GEMM3 across node halves ----
    cudaStreamWaitEvent(0, evC, 0);
    k_comb_sage<<<H0B, 256>>>(p_Pl, p_Pr, bl0, p_h2, 0);
    cudaEventRecord(evD, 0);
    k_comb_sage<<<H1B, 256>>>(p_Pl, p_Pr, bl0, p_h2, H0N);
    cudaEventRecord(evE, 0);

    cudaStreamWaitEvent(s_aux, evD, 0);
    k_mma<<<dim3(4, H0M), 256, SMEM_BYTES, s_aux>>>(p_h2, p_w1, HH, 512,
                                                    p_Pl, p_Pr, NN, 0);
    cudaStreamWaitEvent(s_aux, evE, 0);
    k_mma<<<dim3(4, H1M), 256, SMEM_BYTES, s_aux>>>(p_h2, p_w1, HH, 512,
                                                    p_Pl, p_Pr, NN, H0N);
    cudaEventRecord(evF, s_aux);

    // ---- final combine + head ----
    cudaStreamWaitEvent(0, evF, 0);
    k_comb_sage_out<<<NCB, 256>>>(p_Pl, p_Pr, bl1, lw, lb, out);
}

// round 16
// speedup vs baseline: 1.0373x; 1.0373x over previous
#include <cuda_runtime.h>
#include <cuda_fp16.h>
#include <math.h>
#include <stdint.h>

// Problem constants
static const int NN = 50000;
static const int FF = 64;
static const int HH = 256;
static const int EE = 1600000;
static const int FH = 320;                     // FF + HH
static const int NB_SCAN = (NN + 1023) / 1024; // 49
static const int MBLK = (NN + 127) / 128;      // 391
static const int NCB = (NN + 7) / 8;           // 6250 combine blocks

// ---------------- scratch (__device__ globals; allocation-free) ----------------
__device__ int   d_cnt[NN];
__device__ int   d_rowptr[NN + 1];
__device__ int   d_fill[NN];
__device__ int   d_col[EE];
__device__ int   d_bsum[64];
__device__ float d_deg[NN];
__device__ float d_g1[NN];
// fp16 activation buffers (GEMM A operands)
__device__ __align__(16) __half d_h1[NN * HH];    // tanh(gin0)
__device__ __align__(16) __half d_hcat[NN * FH];  // [x | h1b]
__device__ __align__(16) __half d_h2[NN * HH];    // relu(sage0)
// fp16 projection outputs
__device__ __align__(16) __half d_Pl[NN * HH];
__device__ __align__(16) __half d_Pr[NN * HH];
// fp16 weights
__device__ __align__(16) __half d_gw1[HH * HH];     // [256,256]
__device__ __align__(16) __half d_w0[FH * 2 * HH];  // [320,512] = [Wl0|Wr0]
__device__ __align__(16) __half d_w1[HH * 2 * HH];  // [256,512] = [Wl1|Wr1]

// HW tanh (sm_75+): single MUFU op, ~2^-11 accuracy
__device__ __forceinline__ float htanh(float x) {
    float r;
    asm("tanh.approx.f32 %0, %1;" : "=f"(r) : "f"(x));
    return r;
}

// ---------------- CSR build ----------------
// merged: degree count + GIN0 scatter (one edge-list pass, 2 edges/thread)
__global__ void k_count_g1(const int* __restrict__ src, const int* __restrict__ dst,
                           const float* __restrict__ x1) {
    int t = blockIdx.x * blockDim.x + threadIdx.x;
    int e = t * 2;
    if (e + 1 < EE) {
        int2 s2 = *(const int2*)&src[e];
        int2 d2 = *(const int2*)&dst[e];
        atomicAdd(&d_cnt[d2.x], 1);
        atomicAdd(&d_g1[d2.x], x1[s2.x]);
        atomicAdd(&d_cnt[d2.y], 1);
        atomicAdd(&d_g1[d2.y], x1[s2.y]);
    } else if (e < EE) {
        int d = dst[e];
        atomicAdd(&d_cnt[d], 1);
        atomicAdd(&d_g1[d], x1[src[e]]);
    }
}

__global__ void k_scan1() {
    __shared__ int sh[1024];
    int tid = threadIdx.x;
    int i = blockIdx.x * 1024 + tid;
    int v = (i < NN) ? d_cnt[i] : 0;
    sh[tid] = v;
    __syncthreads();
#pragma unroll
    for (int off = 1; off < 1024; off <<= 1) {
        int t = (tid >= off) ? sh[tid - off] : 0;
        __syncthreads();
        sh[tid] += t;
        __syncthreads();
    }
    if (i < NN) d_rowptr[i] = sh[tid] - v; // exclusive
    if (tid == 1023) d_bsum[blockIdx.x] = sh[1023];
}

// scan3 with scan2 folded in: each block redundantly prefix-sums the 49 block sums
__global__ void k_scan3() {
    __shared__ int s_pre[NB_SCAN];
    if (threadIdx.x == 0) {
        int run = 0;
#pragma unroll 1
        for (int b = 0; b < NB_SCAN; b++) {
            int t = d_bsum[b];
            s_pre[b] = run;
            run += t;
        }
    }
    __syncthreads();
    int i = blockIdx.x * blockDim.x + threadIdx.x;
    if (i < NN) {
        int r = d_rowptr[i] + s_pre[i >> 10];
        d_rowptr[i] = r;
        d_fill[i] = r;
        float c = (float)d_cnt[i];
        d_deg[i] = fmaxf(c, 1.0f);
    } else if (i == NN) {
        d_rowptr[NN] = EE;
    }
}

__global__ void k_fill(const int* __restrict__ src, const int* __restrict__ dst) {
    int e = blockIdx.x * blockDim.x + threadIdx.x;
    if (e < EE) {
        int pos = atomicAdd(&d_fill[dst[e]], 1);
        d_col[pos] = src[e];
    }
}

// ---------------- weight convert (all 5 weights in one kernel) ----------------
__global__ void k_cvt_all(const float* __restrict__ gw1,
                          const float* __restrict__ wl0, const float* __restrict__ wr0,
                          const float* __restrict__ wl1, const float* __restrict__ wr1) {
    int i = blockIdx.x * blockDim.x + threadIdx.x;
    if (i >= 360448) return;
    const float* W; __half* D; int pitch, off, base;
    if (i < 65536)       { W = gw1; D = d_gw1; pitch = 256; off = 0;   base = 0; }
    else if (i < 147456) { W = wl0; D = d_w0;  pitch = 512; off = 0;   base = 65536; }
    else if (i < 229376) { W = wr0; D = d_w0;  pitch = 512; off = 256; base = 147456; }
    else if (i < 294912) { W = wl1; D = d_w1;  pitch = 512; off = 0;   base = 229376; }
    else                 { W = wr1; D = d_w1;  pitch = 512; off = 256; base = 294912; }
    int j = i - base;
    int k = j >> 8, c = j & 255;
    D[(size_t)k * pitch + off + c] = __float2half_rn(W[j]);
}

// x [N,64] fp32 -> hcat fp16 cols 0..63 (pitch 320)
__global__ void k_split_x(const float* __restrict__ x) {
    int i = blockIdx.x * blockDim.x + threadIdx.x;
    if (i >= NN * FF) return;
    int r = i >> 6;
    int c = i & 63;
    d_hcat[(size_t)r * FH + c] = __float2half_rn(x[i]);
}

// warp per node: h1[node, :] = tanh(g * w0 + b0), 8 cols per lane, uint4 store
__global__ void k_gin0_act(const float* __restrict__ x1,
                           const float* __restrict__ w0, const float* __restrict__ b0) {
    int node = blockIdx.x * 8 + (threadIdx.x >> 5);
    if (node >= NN) return;
    int lane = threadIdx.x & 31;
    float g = d_g1[node] + x1[node]; // self term folded in
    int c = lane * 8;
    const float4* w4 = (const float4*)&w0[c];
    const float4* b4 = (const float4*)&b0[c];
    float4 w_0 = w4[0], w_1 = w4[1];
    float4 b_0 = b4[0], b_1 = b4[1];
    float a[8];
    a[0] = htanh(fmaf(g, w_0.x, b_0.x));
    a[1] = htanh(fmaf(g, w_0.y, b_0.y));
    a[2] = htanh(fmaf(g, w_0.z, b_0.z));
    a[3] = htanh(fmaf(g, w_0.w, b_0.w));
    a[4] = htanh(fmaf(g, w_1.x, b_1.x));
    a[5] = htanh(fmaf(g, w_1.y, b_1.y));
    a[6] = htanh(fmaf(g, w_1.z, b_1.z));
    a[7] = htanh(fmaf(g, w_1.w, b_1.w));
    uint4 r;
    *(__half2*)&r.x = __floats2half2_rn(a[0], a[1]);
    *(__half2*)&r.y = __floats2half2_rn(a[2], a[3]);
    *(__half2*)&r.z = __floats2half2_rn(a[4], a[5]);
    *(__half2*)&r.w = __floats2half2_rn(a[6], a[7]);
    *(uint4*)&d_h1[(size_t)node * HH + c] = r;
}

// ---------------- fused gather + combine (warp per node, uint4 loads) ----------------
__device__ __forceinline__ void acc_u4(float* a, uint4 u) {
    float2 f;
    f = __half22float2(*(__half2*)&u.x); a[0] += f.x; a[1] += f.y;
    f = __half22float2(*(__half2*)&u.y); a[2] += f.x; a[3] += f.y;
    f = __half22float2(*(__half2*)&u.z); a[4] += f.x; a[5] += f.y;
    f = __half22float2(*(__half2*)&u.w); a[6] += f.x; a[7] += f.y;
}

__device__ __forceinline__ void gather_sum(float* a, const uint4* __restrict__ P4,
                                           int beg, int end, int lane) {
    int j = beg;
    for (; j + 3 < end; j += 4) {
        int s0 = d_col[j], s1 = d_col[j + 1], s2 = d_col[j + 2], s3 = d_col[j + 3];
        uint4 u0 = P4[(size_t)s0 * 32 + lane];
        uint4 u1 = P4[(size_t)s1 * 32 + lane];
        uint4 u2 = P4[(size_t)s2 * 32 + lane];
        uint4 u3 = P4[(size_t)s3 * 32 + lane];
        acc_u4(a, u0); acc_u4(a, u1); acc_u4(a, u2); acc_u4(a, u3);
    }
    for (; j < end; j++) acc_u4(a, P4[(size_t)d_col[j] * 32 + lane]);
}

__device__ __forceinline__ uint4 pack8h(const float* a) {
    uint4 r;
    *(__half2*)&r.x = __floats2half2_rn(a[0], a[1]);
    *(__half2*)&r.y = __floats2half2_rn(a[2], a[3]);
    *(__half2*)&r.z = __floats2half2_rn(a[4], a[5]);
    *(__half2*)&r.w = __floats2half2_rn(a[6], a[7]);
    return r;
}

// GIN1: hcat[64..319] = tanh(P[node] + sum_nbr P[nbr] + b)
__global__ void k_comb_gin(const __half* __restrict__ P,
                           const float* __restrict__ bias) {
    int node = blockIdx.x * 8 + (threadIdx.x >> 5);
    if (node >= NN) return;
    int lane = threadIdx.x & 31;
    const uint4* P4 = (const uint4*)P;
    float a[8] = {0, 0, 0, 0, 0, 0, 0, 0};
    gather_sum(a, P4, d_rowptr[node], d_rowptr[node + 1], lane);
    acc_u4(a, P4[(size_t)node * 32 + lane]); // self
    const float4* b4 = (const float4*)&bias[lane * 8];
    float4 b0 = b4[0], b1 = b4[1];
    a[0] = htanh(a[0] + b0.x); a[1] = htanh(a[1] + b0.y);
    a[2] = htanh(a[2] + b0.z); a[3] = htanh(a[3] + b0.w);
    a[4] = htanh(a[4] + b1.x); a[5] = htanh(a[5] + b1.y);
    a[6] = htanh(a[6] + b1.z); a[7] = htanh(a[7] + b1.w);
    *(uint4*)&d_hcat[(size_t)node * FH + 64 + lane * 8] = pack8h(a);
}

// SAGE: out = relu(sum_nbr Pl[nbr]/deg + b + Pr[node])
__global__ void k_comb_sage(const __half* __restrict__ Pl,
                            const __half* __restrict__ Pr,
                            const float* __restrict__ bias,
                            __half* __restrict__ outp) {
    int node = blockIdx.x * 8 + (threadIdx.x >> 5);
    if (node >= NN) return;
    int lane = threadIdx.x & 31;
    const uint4* Pl4 = (const uint4*)Pl;
    const uint4* Pr4 = (const uint4*)Pr;
    float a[8] = {0, 0, 0, 0, 0, 0, 0, 0};
    gather_sum(a, Pl4, d_rowptr[node], d_rowptr[node + 1], lane);
    float inv = 1.0f / d_deg[node];
    float r[8] = {0, 0, 0, 0, 0, 0, 0, 0};
    acc_u4(r, Pr4[(size_t)node * 32 + lane]);
    const float4* b4 = (const float4*)&bias[lane * 8];
    float4 b0 = b4[0], b1 = b4[1];
    a[0] = fmaxf(a[0] * inv + b0.x + r[0], 0.f);
    a[1] = fmaxf(a[1] * inv + b0.y + r[1], 0.f);
    a[2] = fmaxf(a[2] * inv + b0.z + r[2], 0.f);
    a[3] = fmaxf(a[3] * inv + b0.w + r[3], 0.f);
    a[4] = fmaxf(a[4] * inv + b1.x + r[4], 0.f);
    a[5] = fmaxf(a[5] * inv + b1.y + r[5], 0.f);
    a[6] = fmaxf(a[6] * inv + b1.z + r[6], 0.f);
    a[7] = fmaxf(a[7] * inv + b1.w + r[7], 0.f);
    *(uint4*)&outp[(size_t)node * HH + lane * 8] = pack8h(a);
}

// SAGE final + fused head: out[node] = relu(...) . lw + lb  (256 -> 2)
__global__ void k_comb_sage_out(const __half* __restrict__ Pl,
                                const __half* __restrict__ Pr,
                                const float* __restrict__ bias,
                                const float* __restrict__ lw,
                                const float* __restrict__ lb,
                                float* __restrict__ out) {
    int node = blockIdx.x * 8 + (threadIdx.x >> 5);
    if (node >= NN) return;
    int lane = threadIdx.x & 31;
    const uint4* Pl4 = (const uint4*)Pl;
    const uint4* Pr4 = (const uint4*)Pr;
    float a[8] = {0, 0, 0, 0, 0, 0, 0, 0};
    gather_sum(a, Pl4, d_rowptr[node], d_rowptr[node + 1], lane);
    float inv = 1.0f / d_deg[node];
    float r[8] = {0, 0, 0, 0, 0, 0, 0, 0};
    acc_u4(r, Pr4[(size_t)node * 32 + lane]);
    const float4* b4 = (const float4*)&bias[lane * 8];
    float4 b0 = b4[0], b1 = b4[1];
    a[0] = fmaxf(a[0] * inv + b0.x + r[0], 0.f);
    a[1] = fmaxf(a[1] * inv + b0.y + r[1], 0.f);
    a[2] = fmaxf(a[2] * inv + b0.z + r[2], 0.f);
    a[3] = fmaxf(a[3] * inv + b0.w + r[3], 0.f);
    a[4] = fmaxf(a[4] * inv + b1.x + r[4], 0.f);
    a[5] = fmaxf(a[5] * inv + b1.y + r[5], 0.f);
    a[6] = fmaxf(a[6] * inv + b1.z + r[6], 0.f);
    a[7] = fmaxf(a[7] * inv + b1.w + r[7], 0.f);
    int c = lane * 8;
    float p0 = 0.f, p1 = 0.f;
#pragma unroll
    for (int i = 0; i < 8; i++) {
        p0 += a[i] * lw[(c + i) * 2 + 0];
        p1 += a[i] * lw[(c + i) * 2 + 1];
    }
#pragma unroll
    for (int o = 16; o > 0; o >>= 1) {
        p0 += __shfl_down_sync(0xFFFFFFFFu, p0, o);
        p1 += __shfl_down_sync(0xFFFFFFFFu, p1, o);
    }
    if (lane == 0) {
        out[node * 2 + 0] = p0 + lb[0];
        out[node * 2 + 1] = p1 + lb[1];
    }
}

// ---------------- fp16 tensor-core GEMM, single weight panel, 3-stage pipeline ----------------
#define CP_ASYNC16(dst, src, sz) \
    asm volatile("cp.async.cg.shared.global [%0], [%1], 16, %2;" \
                 :: "r"(dst), "l"(src), "r"(sz))
#define CP_COMMIT() asm volatile("cp.async.commit_group;")
#define CP_WAIT2()  asm volatile("cp.async.wait_group 2;")
#define CP_WAIT1()  asm volatile("cp.async.wait_group 1;")
#define CP_WAIT0()  asm volatile("cp.async.wait_group 0;")

static const int APITCH = 40;   // halves per A row (32 data + 8 pad)
static const int BPITCH = 136;  // halves per B row (128 data + 8 pad)
static const int AS_ST = 128 * APITCH;   // 5120 halves per A stage
static const int BS_ST = 32 * BPITCH;    // 4352 halves per B stage
static const int B_OFF = 3 * AS_ST;      // 15360
static const int SMEM_BYTES = (3 * AS_ST + 3 * BS_ST) * 2; // 56832

__global__ void __launch_bounds__(256, 2)
k_mma(const __half* __restrict__ A, const __half* __restrict__ B,
      int K, int Nc,
      __half* __restrict__ C0, __half* __restrict__ C1, int M)
{
    extern __shared__ __half sm[];
    const int tid = threadIdx.x;
    const int lane = tid & 31, warp = tid >> 5;
    const int wm = warp >> 1, wn = warp & 1;  // 4 x 2 warp grid, 32x64 per warp
    const int blockRow = blockIdx.y * 128;
    const int blockCol = blockIdx.x * 128;

    const int nIter = K >> 5;   // BK = 32

    uint32_t sm_base = (uint32_t)__cvta_generic_to_shared(sm);

    auto prefetch = [&](int it) {
        int st = it % 3;
        int kk = it << 5;
#pragma unroll
        for (int i = 0; i < 2; i++) {
            int idx = tid + i * 256;
            int row = idx >> 2, ch = idx & 3;
            int gr = blockRow + row;
            int ok = (gr < M) ? 16 : 0;
            const __half* srcp = A + (size_t)(ok ? gr : 0) * K + kk + ch * 8;
            uint32_t dstp = sm_base + (st * AS_ST + row * APITCH + ch * 8) * 2;
            CP_ASYNC16(dstp, srcp, ok);
        }
#pragma unroll
        for (int i = 0; i < 2; i++) {
            int idx = tid + i * 256;
            int row = idx >> 4, ch = idx & 15;
            const __half* srcp = B + (size_t)(kk + row) * Nc + blockCol + ch * 8;
            uint32_t dstp = sm_base + (B_OFF + st * BS_ST + row * BPITCH + ch * 8) * 2;
            CP_ASYNC16(dstp, srcp, 16);
        }
    };

    float c[2][8][4];
#pragma unroll
    for (int mt = 0; mt < 2; mt++)
#pragma unroll
        for (int nt = 0; nt < 8; nt++)
#pragma unroll
            for (int q = 0; q < 4; q++) c[mt][nt][q] = 0.f;

    prefetch(0); CP_COMMIT();
    if (nIter > 1) { prefetch(1); CP_COMMIT(); }

#pragma unroll 1
    for (int it = 0; it < nIter; it++) {
        if (it + 2 < nIter) {
            prefetch(it + 2);
            CP_COMMIT();
            CP_WAIT2();
        } else if (it + 1 < nIter) {
            CP_WAIT1();
        } else {
            CP_WAIT0();
        }
        __syncthreads();

        const int st = it % 3;
        const __half* as = sm + st * AS_ST;
        const __half* bs = sm + B_OFF + st * BS_ST;
#pragma unroll
        for (int ks = 0; ks < 2; ks++) {
            uint32_t af[2][4], bfr[4][4];
#pragma unroll
            for (int mt = 0; mt < 2; mt++) {
                int row = wm * 32 + mt * 16 + (lane & 15);
                int col = ks * 16 + (lane >> 4) * 8;
                uint32_t addr = (uint32_t)__cvta_generic_to_shared(&as[row * APITCH + col]);
                asm volatile(
                    "ldmatrix.sync.aligned.m8n8.x4.shared.b16 {%0,%1,%2,%3}, [%4];"
                    : "=r"(af[mt][0]), "=r"(af[mt][1]), "=r"(af[mt][2]), "=r"(af[mt][3])
                    : "r"(addr));
            }
#pragma unroll
            for (int bt = 0; bt < 4; bt++) {
                int row = ks * 16 + (lane & 15);
                int col = wn * 64 + bt * 16 + (lane >> 4) * 8;
                uint32_t addr = (uint32_t)__cvta_generic_to_shared(&bs[row * BPITCH + col]);
                asm volatile(
                    "ldmatrix.sync.aligned.m8n8.x4.trans.shared.b16 {%0,%1,%2,%3}, [%4];"
                    : "=r"(bfr[bt][0]), "=r"(bfr[bt][1]), "=r"(bfr[bt][2]), "=r"(bfr[bt][3])
                    : "r"(addr));
            }
#pragma unroll
            for (int mt = 0; mt < 2; mt++)
#pragma unroll
                for (int nt = 0; nt < 8; nt++) {
                    const uint32_t b0 = bfr[nt >> 1][(nt & 1) * 2];
                    const uint32_t b1 = bfr[nt >> 1][(nt & 1) * 2 + 1];
                    asm volatile(
                        "mma.sync.aligned.m16n8k16.row.col.f32.f16.f16.f32 "
                        "{%0,%1,%2,%3}, {%4,%5,%6,%7}, {%8,%9}, {%0,%1,%2,%3};"
                        : "+f"(c[mt][nt][0]), "+f"(c[mt][nt][1]),
                          "+f"(c[mt][nt][2]), "+f"(c[mt][nt][3])
                        : "r"(af[mt][0]), "r"(af[mt][1]), "r"(af[mt][2]), "r"(af[mt][3]),
                          "r"(b0), "r"(b1));
                }
        }
        __syncthreads();
    }

    // epilogue: fp16 stores
#pragma unroll
    for (int mt = 0; mt < 2; mt++) {
#pragma unroll
        for (int half_ = 0; half_ < 2; half_++) {
            int row = blockRow + wm * 32 + mt * 16 + half_ * 8 + (lane >> 2);
            if (row >= M) continue;
#pragma unroll
            for (int nt = 0; nt < 8; nt++) {
                int gcol = blockCol + wn * 64 + nt * 8 + (lane & 3) * 2;
                __half2 hv = __floats2half2_rn(c[mt][nt][half_ * 2 + 0],
                                               c[mt][nt][half_ * 2 + 1]);
                __half* Cp = (gcol < 256) ? C0 : C1;
                int cc = gcol & 255;
                *(__half2*)&Cp[(size_t)row * 256 + cc] = hv;
            }
        }
    }
}

// ---------------- launch ----------------
extern "C" void kernel_launch(void* const* d_in, const int* in_sizes, int n_in,
                              void* d_out, int out_size) {
    (void)in_sizes; (void)n_in; (void)out_size;
    const float* x   = (const float*)d_in[0];
    const float* x1  = (const float*)d_in[1];
    const int*   ei  = (const int*)d_in[2];
    const int*   src = ei;
    const int*   dst = ei + EE;
    const float* gw0 = (const float*)d_in[3];
    const float* gb0 = (const float*)d_in[4];
    const float* gw1 = (const float*)d_in[5];
    const float* gb1 = (const float*)d_in[6];
    const float* wl0 = (const float*)d_in[7];
    const float* bl0 = (const float*)d_in[8];
    const float* wr0 = (const float*)d_in[9];
    const float* wl1 = (const float*)d_in[10];
    const float* bl1 = (const float*)d_in[11];
    const float* wr1 = (const float*)d_in[12];
    const float* lw  = (const float*)d_in[13];
    const float* lb  = (const float*)d_in[14];
    float* out = (float*)d_out;

    cudaFuncSetAttribute(k_mma, cudaFuncAttributeMaxDynamicSharedMemorySize, SMEM_BYTES);

    __half *p_h1, *p_hcat, *p_h2, *p_Pl, *p_Pr, *p_gw1, *p_w0, *p_w1;
    cudaGetSymbolAddress((void**)&p_h1, d_h1);
    cudaGetSymbolAddress((void**)&p_hcat, d_hcat);
    cudaGetSymbolAddress((void**)&p_h2, d_h2);
    cudaGetSymbolAddress((void**)&p_Pl, d_Pl);
    cudaGetSymbolAddress((void**)&p_Pr, d_Pr);
    cudaGetSymbolAddress((void**)&p_gw1, d_gw1);
    cudaGetSymbolAddress((void**)&p_w0, d_w0);
    cudaGetSymbolAddress((void**)&p_w1, d_w1);

    void *p_cnt, *p_g1;
    cudaGetSymbolAddress(&p_cnt, d_cnt);
    cudaGetSymbolAddress(&p_g1, d_g1);

    // one-time aux stream + events
    static cudaStream_t s_aux = nullptr;
    static cudaEvent_t ev_fork = nullptr, ev_join = nullptr, ev_g1 = nullptr;
    if (s_aux == nullptr) {
        cudaStreamCreateWithFlags(&s_aux, cudaStreamNonBlocking);
        cudaEventCreateWithFlags(&ev_fork, cudaEventDisableTiming);
        cudaEventCreateWithFlags(&ev_join, cudaEventDisableTiming);
        cudaEventCreateWithFlags(&ev_g1, cudaEventDisableTiming);
    }

    // ---- fork ----
    cudaEventRecord(ev_fork, 0);
    cudaStreamWaitEvent(s_aux, ev_fork, 0);

    // aux: weight cvt + x split (independent of CSR/g1)
    k_cvt_all<<<(360448 + 255) / 256, 256, 0, s_aux>>>(gw1, wl0, wr0, wl1, wr1);
    k_split_x<<<(NN * FF + 255) / 256, 256, 0, s_aux>>>(x);

    // main: merged count + g1 scatter (one edge pass), then scan/fill
    cudaMemsetAsync(p_cnt, 0, NN * sizeof(int), 0);
    cudaMemsetAsync(p_g1, 0, NN * sizeof(float), 0);
    k_count_g1<<<(EE / 2 + 255) / 256, 256>>>(src, dst, x1);
    cudaEventRecord(ev_g1, 0);
    k_scan1<<<NB_SCAN, 1024>>>();
    k_scan3<<<(NN + 1 + 255) / 256, 256>>>();
    k_fill<<<(EE + 255) / 256, 256>>>(src, dst);

    // aux: gin0 + GEMM1 once g1 is ready (overlaps scan/fill on main)
    cudaStreamWaitEvent(s_aux, ev_g1, 0);
    k_gin0_act<<<NCB, 256, 0, s_aux>>>(x1, gw0, gb0);
    k_mma<<<dim3(2, MBLK), 256, SMEM_BYTES, s_aux>>>(p_h1, p_gw1, HH, HH,
                                                     p_Pl, nullptr, NN);
    cudaEventRecord(ev_join, s_aux);

    // ---- join ----
    cudaStreamWaitEvent(0, ev_join, 0);

    // GIN layer 1 combine
    k_comb_gin<<<NCB, 256>>>(p_Pl, gb1);

    // SAGE layer 0
    k_mma<<<dim3(4, MBLK), 256, SMEM_BYTES>>>(p_hcat, p_w0, FH, 512, p_Pl, p_Pr, NN);
    k_comb_sage<<<NCB, 256>>>(p_Pl, p_Pr, bl0, p_h2);

    // SAGE layer 1 + output head
    k_mma<<<dim3(4, MBLK), 256, SMEM_BYTES>>>(p_h2, p_w1, HH, 512, p_Pl, p_Pr, NN);
    k_comb_sage_out<<<NCB, 256>>>(p_Pl, p_Pr, bl1, lw, lb, out);
}

// round 17
// speedup vs baseline: 1.0528x; 1.0150x over previous
#include <cuda_runtime.h>
#include <cuda_fp16.h>
#include <math.h>
#include <stdint.h>

// Problem constants
static const int NN = 50000;
static const int FF = 64;
static const int HH = 256;
static const int EE = 1600000;
static const int FH = 320;                     // FF + HH
static const int NB_SCAN = (NN + 1023) / 1024; // 49
static const int MBLK = (NN + 127) / 128;      // 391
static const int NCB = (NN + 7) / 8;           // 6250 combine blocks

// ---------------- scratch (__device__ globals; allocation-free) ----------------
__device__ int   d_cnt[NN];
__device__ int   d_rowptr[NN + 1];
__device__ int   d_fill[NN];
__device__ int   d_col[EE];
__device__ int   d_bsum[64];
__device__ float d_deg[NN];
__device__ float d_g1[NN];
// fp16 activation buffers (GEMM A operands)
__device__ __align__(16) __half d_h1[NN * HH];    // tanh(gin0)
__device__ __align__(16) __half d_hcat[NN * FH];  // [x | h1b]
__device__ __align__(16) __half d_h2[NN * HH];    // relu(sage0)
// fp16 projection outputs
__device__ __align__(16) __half d_Pl[NN * HH];
__device__ __align__(16) __half d_Pr[NN * HH];
// fp16 weights
__device__ __align__(16) __half d_gw1[HH * HH];     // [256,256]
__device__ __align__(16) __half d_w0[FH * 2 * HH];  // [320,512] = [Wl0|Wr0]
__device__ __align__(16) __half d_w1[HH * 2 * HH];  // [256,512] = [Wl1|Wr1]

// HW tanh (sm_75+): single MUFU op, ~2^-11 accuracy
__device__ __forceinline__ float htanh(float x) {
    float r;
    asm("tanh.approx.f32 %0, %1;" : "=f"(r) : "f"(x));
    return r;
}

// ---------------- CSR build ----------------
// merged: degree count + GIN0 scatter (one edge-list pass)
__global__ void k_count_g1(const int* __restrict__ src, const int* __restrict__ dst,
                           const float* __restrict__ x1) {
    int e = blockIdx.x * blockDim.x + threadIdx.x;
    if (e < EE) {
        int d = dst[e];
        atomicAdd(&d_cnt[d], 1);
        atomicAdd(&d_g1[d], x1[src[e]]);
    }
}

__global__ void k_scan1() {
    __shared__ int sh[1024];
    int tid = threadIdx.x;
    int i = blockIdx.x * 1024 + tid;
    int v = (i < NN) ? d_cnt[i] : 0;
    sh[tid] = v;
    __syncthreads();
#pragma unroll
    for (int off = 1; off < 1024; off <<= 1) {
        int t = (tid >= off) ? sh[tid - off] : 0;
        __syncthreads();
        sh[tid] += t;
        __syncthreads();
    }
    if (i < NN) d_rowptr[i] = sh[tid] - v; // exclusive
    if (tid == 1023) d_bsum[blockIdx.x] = sh[1023];
}

// scan3 with scan2 folded in: each block redundantly prefix-sums the 49 block sums
__global__ void k_scan3() {
    __shared__ int s_pre[NB_SCAN];
    if (threadIdx.x == 0) {
        int run = 0;
#pragma unroll 1
        for (int b = 0; b < NB_SCAN; b++) {
            int t = d_bsum[b];
            s_pre[b] = run;
            run += t;
        }
    }
    __syncthreads();
    int i = blockIdx.x * blockDim.x + threadIdx.x;
    if (i < NN) {
        int r = d_rowptr[i] + s_pre[i >> 10];
        d_rowptr[i] = r;
        d_fill[i] = r;
        float c = (float)d_cnt[i];
        d_deg[i] = fmaxf(c, 1.0f);
    } else if (i == NN) {
        d_rowptr[NN] = EE;
    }
}

// fill: 2 edges per thread, int2 loads
__global__ void k_fill(const int* __restrict__ src, const int* __restrict__ dst) {
    int t = blockIdx.x * blockDim.x + threadIdx.x;
    int e = t * 2;
    if (e + 1 < EE) {
        int2 s2 = *(const int2*)&src[e];
        int2 d2 = *(const int2*)&dst[e];
        int p0 = atomicAdd(&d_fill[d2.x], 1);
        d_col[p0] = s2.x;
        int p1 = atomicAdd(&d_fill[d2.y], 1);
        d_col[p1] = s2.y;
    } else if (e < EE) {
        int pos = atomicAdd(&d_fill[dst[e]], 1);
        d_col[pos] = src[e];
    }
}

// ---------------- weight convert (all 5 weights in one kernel) ----------------
__global__ void k_cvt_all(const float* __restrict__ gw1,
                          const float* __restrict__ wl0, const float* __restrict__ wr0,
                          const float* __restrict__ wl1, const float* __restrict__ wr1) {
    int i = blockIdx.x * blockDim.x + threadIdx.x;
    if (i >= 360448) return;
    const float* W; __half* D; int pitch, off, base;
    if (i < 65536)       { W = gw1; D = d_gw1; pitch = 256; off = 0;   base = 0; }
    else if (i < 147456) { W = wl0; D = d_w0;  pitch = 512; off = 0;   base = 65536; }
    else if (i < 229376) { W = wr0; D = d_w0;  pitch = 512; off = 256; base = 147456; }
    else if (i < 294912) { W = wl1; D = d_w1;  pitch = 512; off = 0;   base = 229376; }
    else                 { W = wr1; D = d_w1;  pitch = 512; off = 256; base = 294912; }
    int j = i - base;
    int k = j >> 8, c = j & 255;
    D[(size_t)k * pitch + off + c] = __float2half_rn(W[j]);
}

// x [N,64] fp32 -> hcat fp16 cols 0..63 (pitch 320); 4 cols per thread
__global__ void k_split_x(const float* __restrict__ x) {
    int i = blockIdx.x * blockDim.x + threadIdx.x; // i over NN*16 quads
    if (i >= NN * 16) return;
    int r = i >> 4;
    int c = (i & 15) * 4;
    float4 v = *(const float4*)&x[r * FF + c];
    uint2 o;
    *(__half2*)&o.x = __floats2half2_rn(v.x, v.y);
    *(__half2*)&o.y = __floats2half2_rn(v.z, v.w);
    *(uint2*)&d_hcat[(size_t)r * FH + c] = o;
}

// warp per node: h1[node, :] = tanh(g * w0 + b0), 8 cols per lane, uint4 store
__global__ void k_gin0_act(const float* __restrict__ x1,
                           const float* __restrict__ w0, const float* __restrict__ b0) {
    int node = blockIdx.x * 8 + (threadIdx.x >> 5);
    if (node >= NN) return;
    int lane = threadIdx.x & 31;
    float g = d_g1[node] + x1[node]; // self term folded in
    int c = lane * 8;
    const float4* w4 = (const float4*)&w0[c];
    const float4* b4 = (const float4*)&b0[c];
    float4 w_0 = w4[0], w_1 = w4[1];
    float4 b_0 = b4[0], b_1 = b4[1];
    float a[8];
    a[0] = htanh(fmaf(g, w_0.x, b_0.x));
    a[1] = htanh(fmaf(g, w_0.y, b_0.y));
    a[2] = htanh(fmaf(g, w_0.z, b_0.z));
    a[3] = htanh(fmaf(g, w_0.w, b_0.w));
    a[4] = htanh(fmaf(g, w_1.x, b_1.x));
    a[5] = htanh(fmaf(g, w_1.y, b_1.y));
    a[6] = htanh(fmaf(g, w_1.z, b_1.z));
    a[7] = htanh(fmaf(g, w_1.w, b_1.w));
    uint4 r;
    *(__half2*)&r.x = __floats2half2_rn(a[0], a[1]);
    *(__half2*)&r.y = __floats2half2_rn(a[2], a[3]);
    *(__half2*)&r.z = __floats2half2_rn(a[4], a[5]);
    *(__half2*)&r.w = __floats2half2_rn(a[6], a[7]);
    *(uint4*)&d_h1[(size_t)node * HH + c] = r;
}

// ---------------- fused gather + combine (warp per node, uint4 loads) ----------------
__device__ __forceinline__ void acc_u4(float* a, uint4 u) {
    float2 f;
    f = __half22float2(*(__half2*)&u.x); a[0] += f.x; a[1] += f.y;
    f = __half22float2(*(__half2*)&u.y); a[2] += f.x; a[3] += f.y;
    f = __half22float2(*(__half2*)&u.z); a[4] += f.x; a[5] += f.y;
    f = __half22float2(*(__half2*)&u.w); a[6] += f.x; a[7] += f.y;
}

__device__ __forceinline__ void gather_sum(float* a, const uint4* __restrict__ P4,
                                           int beg, int end, int lane) {
    int j = beg;
    for (; j + 3 < end; j += 4) {
        int s0 = d_col[j], s1 = d_col[j + 1], s2 = d_col[j + 2], s3 = d_col[j + 3];
        uint4 u0 = P4[(size_t)s0 * 32 + lane];
        uint4 u1 = P4[(size_t)s1 * 32 + lane];
        uint4 u2 = P4[(size_t)s2 * 32 + lane];
        uint4 u3 = P4[(size_t)s3 * 32 + lane];
        acc_u4(a, u0); acc_u4(a, u1); acc_u4(a, u2); acc_u4(a, u3);
    }
    for (; j < end; j++) acc_u4(a, P4[(size_t)d_col[j] * 32 + lane]);
}

__device__ __forceinline__ uint4 pack8h(const float* a) {
    uint4 r;
    *(__half2*)&r.x = __floats2half2_rn(a[0], a[1]);
    *(__half2*)&r.y = __floats2half2_rn(a[2], a[3]);
    *(__half2*)&r.z = __floats2half2_rn(a[4], a[5]);
    *(__half2*)&r.w = __floats2half2_rn(a[6], a[7]);
    return r;
}

// GIN1: hcat[64..319] = tanh(P[node] + sum_nbr P[nbr] + b)
__global__ void k_comb_gin(const __half* __restrict__ P,
                           const float* __restrict__ bias) {
    int node = blockIdx.x * 8 + (threadIdx.x >> 5);
    if (node >= NN) return;
    int lane = threadIdx.x & 31;
    const uint4* P4 = (const uint4*)P;
    float a[8] = {0, 0, 0, 0, 0, 0, 0, 0};
    gather_sum(a, P4, d_rowptr[node], d_rowptr[node + 1], lane);
    acc_u4(a, P4[(size_t)node * 32 + lane]); // self
    const float4* b4 = (const float4*)&bias[lane * 8];
    float4 b0 = b4[0], b1 = b4[1];
    a[0] = htanh(a[0] + b0.x); a[1] = htanh(a[1] + b0.y);
    a[2] = htanh(a[2] + b0.z); a[3] = htanh(a[3] + b0.w);
    a[4] = htanh(a[4] + b1.x); a[5] = htanh(a[5] + b1.y);
    a[6] = htanh(a[6] + b1.z); a[7] = htanh(a[7] + b1.w);
    *(uint4*)&d_hcat[(size_t)node * FH + 64 + lane * 8] = pack8h(a);
}

// SAGE: out = relu(sum_nbr Pl[nbr]/deg + b + Pr[node])
__global__ void k_comb_sage(const __half* __restrict__ Pl,
                            const __half* __restrict__ Pr,
                            const float* __restrict__ bias,
                            __half* __restrict__ outp) {
    int node = blockIdx.x * 8 + (threadIdx.x >> 5);
    if (node >= NN) return;
    int lane = threadIdx.x & 31;
    const uint4* Pl4 = (const uint4*)Pl;
    const uint4* Pr4 = (const uint4*)Pr;
    float a[8] = {0, 0, 0, 0, 0, 0, 0, 0};
    gather_sum(a, Pl4, d_rowptr[node], d_rowptr[node + 1], lane);
    float inv = 1.0f / d_deg[node];
    float r[8] = {0, 0, 0, 0, 0, 0, 0, 0};
    acc_u4(r, Pr4[(size_t)node * 32 + lane]);
    const float4* b4 = (const float4*)&bias[lane * 8];
    float4 b0 = b4[0], b1 = b4[1];
    a[0] = fmaxf(a[0] * inv + b0.x + r[0], 0.f);
    a[1] = fmaxf(a[1] * inv + b0.y + r[1], 0.f);
    a[2] = fmaxf(a[2] * inv + b0.z + r[2], 0.f);
    a[3] = fmaxf(a[3] * inv + b0.w + r[3], 0.f);
    a[4] = fmaxf(a[4] * inv + b1.x + r[4], 0.f);
    a[5] = fmaxf(a[5] * inv + b1.y + r[5], 0.f);
    a[6] = fmaxf(a[6] * inv + b1.z + r[6], 0.f);
    a[7] = fmaxf(a[7] * inv + b1.w + r[7], 0.f);
    *(uint4*)&outp[(size_t)node * HH + lane * 8] = pack8h(a);
}

// SAGE final + fused head: out[node] = relu(...) . lw + lb  (256 -> 2)
__global__ void k_comb_sage_out(const __half* __restrict__ Pl,
                                const __half* __restrict__ Pr,
                                const float* __restrict__ bias,
                                const float* __restrict__ lw,
                                const float* __restrict__ lb,
                                float* __restrict__ out) {
    int node = blockIdx.x * 8 + (threadIdx.x >> 5);
    if (node >= NN) return;
    int lane = threadIdx.x & 31;
    const uint4* Pl4 = (const uint4*)Pl;
    const uint4* Pr4 = (const uint4*)Pr;
    float a[8] = {0, 0, 0, 0, 0, 0, 0, 0};
    gather_sum(a, Pl4, d_rowptr[node], d_rowptr[node + 1], lane);
    float inv = 1.0f / d_deg[node];
    float r[8] = {0, 0, 0, 0, 0, 0, 0, 0};
    acc_u4(r, Pr4[(size_t)node * 32 + lane]);
    const float4* b4 = (const float4*)&bias[lane * 8];
    float4 b0 = b4[0], b1 = b4[1];
    a[0] = fmaxf(a[0] * inv + b0.x + r[0], 0.f);
    a[1] = fmaxf(a[1] * inv + b0.y + r[1], 0.f);
    a[2] = fmaxf(a[2] * inv + b0.z + r[2], 0.f);
    a[3] = fmaxf(a[3] * inv + b0.w + r[3], 0.f);
    a[4] = fmaxf(a[4] * inv + b1.x + r[4], 0.f);
    a[5] = fmaxf(a[5] * inv + b1.y + r[5], 0.f);
    a[6] = fmaxf(a[6] * inv + b1.z + r[6], 0.f);
    a[7] = fmaxf(a[7] * inv + b1.w + r[7], 0.f);
    int c = lane * 8;
    float p0 = 0.f, p1 = 0.f;
#pragma unroll
    for (int i = 0; i < 8; i++) {
        p0 += a[i] * lw[(c + i) * 2 + 0];
        p1 += a[i] * lw[(c + i) * 2 + 1];
    }
#pragma unroll
    for (int o = 16; o > 0; o >>= 1) {
        p0 += __shfl_down_sync(0xFFFFFFFFu, p0, o);
        p1 += __shfl_down_sync(0xFFFFFFFFu, p1, o);
    }
    if (lane == 0) {
        out[node * 2 + 0] = p0 + lb[0];
        out[node * 2 + 1] = p1 + lb[1];
    }
}

// ---------------- fp16 tensor-core GEMM, single weight panel, 3-stage pipeline ----------------
#define CP_ASYNC16(dst, src, sz) \
    asm volatile("cp.async.cg.shared.global [%0], [%1], 16, %2;" \
                 :: "r"(dst), "l"(src), "r"(sz))
#define CP_COMMIT() asm volatile("cp.async.commit_group;")
#define CP_WAIT2()  asm volatile("cp.async.wait_group 2;")
#define CP_WAIT1()  asm volatile("cp.async.wait_group 1;")
#define CP_WAIT0()  asm volatile("cp.async.wait_group 0;")

static const int APITCH = 40;   // halves per A row (32 data + 8 pad)
static const int BPITCH = 136;  // halves per B row (128 data + 8 pad)
static const int AS_ST = 128 * APITCH;   // 5120 halves per A stage
static const int BS_ST = 32 * BPITCH;    // 4352 halves per B stage
static const int B_OFF = 3 * AS_ST;      // 15360
static const int SMEM_BYTES = (3 * AS_ST + 3 * BS_ST) * 2; // 56832

__global__ void __launch_bounds__(256, 2)
k_mma(const __half* __restrict__ A, const __half* __restrict__ B,
      int K, int Nc,
      __half* __restrict__ C0, __half* __restrict__ C1, int M)
{
    extern __shared__ __half sm[];
    const int tid = threadIdx.x;
    const int lane = tid & 31, warp = tid >> 5;
    const int wm = warp >> 1, wn = warp & 1;  // 4 x 2 warp grid, 32x64 per warp
    const int blockRow = blockIdx.y * 128;
    const int blockCol = blockIdx.x * 128;

    const int nIter = K >> 5;   // BK = 32

    uint32_t sm_base = (uint32_t)__cvta_generic_to_shared(sm);

    auto prefetch = [&](int it) {
        int st = it % 3;
        int kk = it << 5;
#pragma unroll
        for (int i = 0; i < 2; i++) {
            int idx = tid + i * 256;
            int row = idx >> 2, ch = idx & 3;
            int gr = blockRow + row;
            int ok = (gr < M) ? 16 : 0;
            const __half* srcp = A + (size_t)(ok ? gr : 0) * K + kk + ch * 8;
            uint32_t dstp = sm_base + (st * AS_ST + row * APITCH + ch * 8) * 2;
            CP_ASYNC16(dstp, srcp, ok);
        }
#pragma unroll
        for (int i = 0; i < 2; i++) {
            int idx = tid + i * 256;
            int row = idx >> 4, ch = idx & 15;
            const __half* srcp = B + (size_t)(kk + row) * Nc + blockCol + ch * 8;
            uint32_t dstp = sm_base + (B_OFF + st * BS_ST + row * BPITCH + ch * 8) * 2;
            CP_ASYNC16(dstp, srcp, 16);
        }
    };

    float c[2][8][4];
#pragma unroll
    for (int mt = 0; mt < 2; mt++)
#pragma unroll
        for (int nt = 0; nt < 8; nt++)
#pragma unroll
            for (int q = 0; q < 4; q++) c[mt][nt][q] = 0.f;

    prefetch(0); CP_COMMIT();
    if (nIter > 1) { prefetch(1); CP_COMMIT(); }

#pragma unroll 1
    for (int it = 0; it < nIter; it++) {
        if (it + 2 < nIter) {
            prefetch(it + 2);
            CP_COMMIT();
            CP_WAIT2();
        } else if (it + 1 < nIter) {
            CP_WAIT1();
        } else {
            CP_WAIT0();
        }
        __syncthreads();

        const int st = it % 3;
        const __half* as = sm + st * AS_ST;
        const __half* bs = sm + B_OFF + st * BS_ST;
#pragma unroll
        for (int ks = 0; ks < 2; ks++) {
            uint32_t af[2][4], bfr[4][4];
#pragma unroll
            for (int mt = 0; mt < 2; mt++) {
                int row = wm * 32 + mt * 16 + (lane & 15);
                int col = ks * 16 + (lane >> 4) * 8;
                uint32_t addr = (uint32_t)__cvta_generic_to_shared(&as[row * APITCH + col]);
                asm volatile(
                    "ldmatrix.sync.aligned.m8n8.x4.shared.b16 {%0,%1,%2,%3}, [%4];"
                    : "=r"(af[mt][0]), "=r"(af[mt][1]), "=r"(af[mt][2]), "=r"(af[mt][3])
                    : "r"(addr));
            }
#pragma unroll
            for (int bt = 0; bt < 4; bt++) {
                int row = ks * 16 + (lane & 15);
                int col = wn * 64 + bt * 16 + (lane >> 4) * 8;
                uint32_t addr = (uint32_t)__cvta_generic_to_shared(&bs[row * BPITCH + col]);
                asm volatile(
                    "ldmatrix.sync.aligned.m8n8.x4.trans.shared.b16 {%0,%1,%2,%3}, [%4];"
                    : "=r"(bfr[bt][0]), "=r"(bfr[bt][1]), "=r"(bfr[bt][2]), "=r"(bfr[bt][3])
                    : "r"(addr));
            }
#pragma unroll
            for (int mt = 0; mt < 2; mt++)
#pragma unroll
                for (int nt = 0; nt < 8; nt++) {
                    const uint32_t b0 = bfr[nt >> 1][(nt & 1) * 2];
                    const uint32_t b1 = bfr[nt >> 1][(nt & 1) * 2 + 1];
                    asm volatile(
                        "mma.sync.aligned.m16n8k16.row.col.f32.f16.f16.f32 "
                        "{%0,%1,%2,%3}, {%4,%5,%6,%7}, {%8,%9}, {%0,%1,%2,%3};"
                        : "+f"(c[mt][nt][0]), "+f"(c[mt][nt][1]),
                          "+f"(c[mt][nt][2]), "+f"(c[mt][nt][3])
                        : "r"(af[mt][0]), "r"(af[mt][1]), "r"(af[mt][2]), "r"(af[mt][3]),
                          "r"(b0), "r"(b1));
                }
        }
        __syncthreads();
    }

    // epilogue: fp16 stores
#pragma unroll
    for (int mt = 0; mt < 2; mt++) {
#pragma unroll
        for (int half_ = 0; half_ < 2; half_++) {
            int row = blockRow + wm * 32 + mt * 16 + half_ * 8 + (lane >> 2);
            if (row >= M) continue;
#pragma unroll
            for (int nt = 0; nt < 8; nt++) {
                int gcol = blockCol + wn * 64 + nt * 8 + (lane & 3) * 2;
                __half2 hv = __floats2half2_rn(c[mt][nt][half_ * 2 + 0],
                                               c[mt][nt][half_ * 2 + 1]);
                __half* Cp = (gcol < 256) ? C0 : C1;
                int cc = gcol & 255;
                *(__half2*)&Cp[(size_t)row * 256 + cc] = hv;
            }
        }
    }
}

// ---------------- launch ----------------
extern "C" void kernel_launch(void* const* d_in, const int* in_sizes, int n_in,
                              void* d_out, int out_size) {
    (void)in_sizes; (void)n_in; (void)out_size;
    const float* x   = (const float*)d_in[0];
    const float* x1  = (const float*)d_in[1];
    const int*   ei  = (const int*)d_in[2];
    const int*   src = ei;
    const int*   dst = ei + EE;
    const float* gw0 = (const float*)d_in[3];
    const float* gb0 = (const float*)d_in[4];
    const float* gw1 = (const float*)d_in[5];
    const float* gb1 = (const float*)d_in[6];
    const float* wl0 = (const float*)d_in[7];
    const float* bl0 = (const float*)d_in[8];
    const float* wr0 = (const float*)d_in[9];
    const float* wl1 = (const float*)d_in[10];
    const float* bl1 = (const float*)d_in[11];
    const float* wr1 = (const float*)d_in[12];
    const float* lw  = (const float*)d_in[13];
    const float* lb  = (const float*)d_in[14];
    float* out = (float*)d_out;

    cudaFuncSetAttribute(k_mma, cudaFuncAttributeMaxDynamicSharedMemorySize, SMEM_BYTES);

    __half *p_h1, *p_hcat, *p_h2, *p_Pl, *p_Pr, *p_gw1, *p_w0, *p_w1;
    cudaGetSymbolAddress((void**)&p_h1, d_h1);
    cudaGetSymbolAddress((void**)&p_hcat, d_hcat);
    cudaGetSymbolAddress((void**)&p_h2, d_h2);
    cudaGetSymbolAddress((void**)&p_Pl, d_Pl);
    cudaGetSymbolAddress((void**)&p_Pr, d_Pr);
    cudaGetSymbolAddress((void**)&p_gw1, d_gw1);
    cudaGetSymbolAddress((void**)&p_w0, d_w0);
    cudaGetSymbolAddress((void**)&p_w1, d_w1);

    void *p_cnt, *p_g1;
    cudaGetSymbolAddress(&p_cnt, d_cnt);
    cudaGetSymbolAddress(&p_g1, d_g1);

    // one-time aux stream + events
    static cudaStream_t s_aux = nullptr;
    static cudaEvent_t ev_fork = nullptr, ev_join = nullptr, ev_g1 = nullptr;
    if (s_aux == nullptr) {
        cudaStreamCreateWithFlags(&s_aux, cudaStreamNonBlocking);
        cudaEventCreateWithFlags(&ev_fork, cudaEventDisableTiming);
        cudaEventCreateWithFlags(&ev_join, cudaEventDisableTiming);
        cudaEventCreateWithFlags(&ev_g1, cudaEventDisableTiming);
    }

    // ---- fork ----
    cudaEventRecord(ev_fork, 0);
    cudaStreamWaitEvent(s_aux, ev_fork, 0);

    // aux: weight cvt + x split (independent of CSR/g1)
    k_cvt_all<<<(360448 + 255) / 256, 256, 0, s_aux>>>(gw1, wl0, wr0, wl1, wr1);
    k_split_x<<<(NN * 16 + 255) / 256, 256, 0, s_aux>>>(x);

    // main: merged count + g1 scatter (one edge pass), then scan/fill
    cudaMemsetAsync(p_cnt, 0, NN * sizeof(int), 0);
    cudaMemsetAsync(p_g1, 0, NN * sizeof(float), 0);
    k_count_g1<<<(EE + 255) / 256, 256>>>(src, dst, x1);
    cudaEventRecord(ev_g1, 0);
    k_scan1<<<NB_SCAN, 1024>>>();
    k_scan3<<<(NN + 1 + 255) / 256, 256>>>();
    k_fill<<<(EE / 2 + 255) / 256, 256>>>(src, dst);

    // aux: gin0 + GEMM1 once g1 is ready (overlaps scan/fill on main)
    cudaStreamWaitEvent(s_aux, ev_g1, 0);
    k_gin0_act<<<NCB, 256, 0, s_aux>>>(x1, gw0, gb0);
    k_mma<<<dim3(2, MBLK), 256, SMEM_BYTES, s_aux>>>(p_h1, p_gw1, HH, HH,
                                                     p_Pl, nullptr, NN);
    cudaEventRecord(ev_join, s_aux);

    // ---- join ----
    cudaStreamWaitEvent(0, ev_join, 0);

    // GIN layer 1 combine
    k_comb_gin<<<NCB, 256>>>(p_Pl, gb1);

    // SAGE layer 0
    k_mma<<<dim3(4, MBLK), 256, SMEM_BYTES>>>(p_hcat, p_w0, FH, 512, p_Pl, p_Pr, NN);
    k_comb_sage<<<NCB, 256>>>(p_Pl, p_Pr, bl0, p_h2);

    // SAGE layer 1 + output head
    k_mma<<<dim3(4, MBLK), 256, SMEM_BYTES>>>(p_h2, p_w1, HH, 512, p_Pl, p_Pr, NN);
    k_comb_sage_out<<<NCB, 256>>>(p_Pl, p_Pr, bl1, lw, lb, out);
}